// round 1
// baseline (speedup 1.0000x reference)
#include <cuda_runtime.h>
#include <math.h>

#define B_   8
#define N_   1024
#define DIM_ 512
#define H_   8
#define DH_  64
#define INNER_ 512
#define SCALE_ 0.125f
#define EPS_ 1e-12f

// ---------------- scratch (static device allocations are allowed) -----------
__device__ float g_q[B_*H_*N_*DH_];      // 16 MB
__device__ float g_k[B_*H_*N_*DH_];      // 16 MB
__device__ float g_v[B_*H_*N_*DH_];      // 16 MB
__device__ float g_att[B_*N_*INNER_];    // 16 MB

// ---------------- kernel 1: qkv = x @ W_qkv, scatter to Q/K/V ---------------
// tiles: BM=64, BN=64, BK=16, 256 threads, 4x4 micro-tile
__global__ void qkv_gemm(const float* __restrict__ x, const float* __restrict__ Wqkv) {
    __shared__ float sA[16][64];   // [k][m]
    __shared__ float sB[16][64];   // [k][n]
    const int tid = threadIdx.x;
    const int m0 = blockIdx.y * 64;
    const int n0 = blockIdx.x * 64;
    const int ty = tid >> 4, tx = tid & 15;

    float acc[4][4] = {};
    const int arow = tid >> 2, akv = (tid & 3) * 4;     // A: 64 rows x 4 float4
    const int brow = tid >> 4, bcol = (tid & 15) * 4;   // B: 16 rows x 16 float4

    for (int k0 = 0; k0 < DIM_; k0 += 16) {
        float4 av = *(const float4*)(x + (size_t)(m0 + arow) * DIM_ + k0 + akv);
        sA[akv+0][arow] = av.x; sA[akv+1][arow] = av.y;
        sA[akv+2][arow] = av.z; sA[akv+3][arow] = av.w;
        float4 bv = *(const float4*)(Wqkv + (size_t)(k0 + brow) * (3*INNER_) + n0 + bcol);
        *(float4*)&sB[brow][bcol] = bv;
        __syncthreads();
        #pragma unroll
        for (int kk = 0; kk < 16; kk++) {
            float a[4], b[4];
            #pragma unroll
            for (int i = 0; i < 4; i++) a[i] = sA[kk][ty*4+i];
            #pragma unroll
            for (int j = 0; j < 4; j++) b[j] = sB[kk][tx*4+j];
            #pragma unroll
            for (int i = 0; i < 4; i++)
                #pragma unroll
                for (int j = 0; j < 4; j++) acc[i][j] += a[i]*b[j];
        }
        __syncthreads();
    }
    #pragma unroll
    for (int i = 0; i < 4; i++) {
        int mg = m0 + ty*4 + i;
        int bb = mg / N_, nn = mg % N_;
        #pragma unroll
        for (int j = 0; j < 4; j++) {
            int cg = n0 + tx*4 + j;
            int sec = cg / INNER_;
            int cc  = cg % INNER_;
            int hh  = cc / DH_, dd = cc % DH_;
            float* dst = (sec == 0) ? g_q : (sec == 1 ? g_k : g_v);
            dst[(((size_t)bb*H_ + hh)*N_ + nn)*DH_ + dd] = acc[i][j];
        }
    }
}

// ---------------- kernel 2: fused attention ---------------------------------
// grid: (N/32, H, B), 256 threads. Dots tile 32x1024 lives in smem.
#define MT_ 32
__global__ void attn_kernel(const float* __restrict__ spd,
                            const float* __restrict__ head_mask) {
    extern __shared__ float smem[];
    float* sQ  = smem;                 // 32*64
    float* sKV = smem + MT_*DH_;       // 64*65 (padded)
    float* sD  = sKV + 64*65;          // 32*1024

    const int bb = blockIdx.z, hh = blockIdx.y;
    const int row0 = blockIdx.x * MT_;
    const int tid = threadIdx.x;
    const int ty = tid >> 5;           // warp id 0..7
    const int tx = tid & 31;           // lane

    const float* Q = g_q + ((size_t)bb*H_ + hh)*N_*DH_;
    const float* K = g_k + ((size_t)bb*H_ + hh)*N_*DH_;
    const float* V = g_v + ((size_t)bb*H_ + hh)*N_*DH_;

    // load Q tile: 2048 floats = 512 float4
    {
        const float4* qs = (const float4*)(Q + (size_t)row0*DH_);
        float4* qd = (float4*)sQ;
        qd[tid]       = qs[tid];
        qd[tid + 256] = qs[tid + 256];
    }

    // ---- phase 1: dots = Q K^T * SCALE into sD ----
    for (int c = 0; c < N_/64; c++) {
        __syncthreads();  // sQ visible (iter 0) / sKV free (iter>0)
        const float4* ks = (const float4*)(K + (size_t)c*64*DH_);
        for (int f = tid; f < 1024; f += 256) {
            float4 v = ks[f];
            int r = f >> 4, c4 = (f & 15) << 2;
            float* d = &sKV[r*65 + c4];
            d[0]=v.x; d[1]=v.y; d[2]=v.z; d[3]=v.w;
        }
        __syncthreads();
        float acc[4][2] = {};
        #pragma unroll
        for (int kk = 0; kk < 64; kk++) {
            float a[4], bv0, bv1;
            #pragma unroll
            for (int i = 0; i < 4; i++) a[i] = sQ[(ty + i*8)*DH_ + kk];
            bv0 = sKV[tx*65 + kk];
            bv1 = sKV[(tx+32)*65 + kk];
            #pragma unroll
            for (int i = 0; i < 4; i++) { acc[i][0] += a[i]*bv0; acc[i][1] += a[i]*bv1; }
        }
        #pragma unroll
        for (int i = 0; i < 4; i++) {
            sD[(ty + i*8)*N_ + c*64 + tx]      = acc[i][0]*SCALE_;
            sD[(ty + i*8)*N_ + c*64 + tx + 32] = acc[i][1]*SCALE_;
        }
    }
    __syncthreads();

    // ---- phase 2: bias + softmax + head-mask rescale, per row (warp/row) ----
    float msum = 0.f;
    #pragma unroll
    for (int i = 0; i < H_; i++) msum += head_mask[i];
    const float scale_m = head_mask[hh] * (float)H_ / msum;

    for (int rr = 0; rr < 4; rr++) {
        const int r  = ty*4 + rr;
        const int rg = row0 + r;
        const float* srow = spd + ((size_t)bb*N_ + rg)*N_;
        float* drow = sD + (size_t)r*N_;

        float accd = 0.f, accp = 0.f;
        for (int j = tx; j < N_; j += 32) {
            float d = drow[j];
            float p = d * srow[j];
            accd += d*d; accp += p*p;
        }
        #pragma unroll
        for (int o = 16; o > 0; o >>= 1) {
            accd += __shfl_xor_sync(0xffffffffu, accd, o);
            accp += __shfl_xor_sync(0xffffffffu, accp, o);
        }
        const float rnorm = sqrtf(accd) / fmaxf(sqrtf(accp), EPS_);

        float mx = -INFINITY;
        for (int j = tx; j < N_; j += 32) {
            float d = drow[j];
            float t = d + d * srow[j] * rnorm;   // dots + normalize(prod)*||dots||
            drow[j] = t;
            mx = fmaxf(mx, t);
        }
        #pragma unroll
        for (int o = 16; o > 0; o >>= 1) mx = fmaxf(mx, __shfl_xor_sync(0xffffffffu, mx, o));

        float s = 0.f;
        for (int j = tx; j < N_; j += 32) {
            float e = __expf(drow[j] - mx);
            drow[j] = e;
            s += e;
        }
        #pragma unroll
        for (int o = 16; o > 0; o >>= 1) s += __shfl_xor_sync(0xffffffffu, s, o);

        const float inv = scale_m / s;
        for (int j = tx; j < N_; j += 32) drow[j] *= inv;
    }
    __syncthreads();

    // ---- phase 3: O = attn @ V ----
    float oacc[4][2] = {};
    for (int c = 0; c < N_/64; c++) {
        const float4* vs = (const float4*)(V + (size_t)c*64*DH_);
        for (int f = tid; f < 1024; f += 256) {
            float4 v = vs[f];
            int r = f >> 4, c4 = (f & 15) << 2;
            float* d = &sKV[r*65 + c4];
            d[0]=v.x; d[1]=v.y; d[2]=v.z; d[3]=v.w;
        }
        __syncthreads();
        #pragma unroll
        for (int kk = 0; kk < 64; kk++) {
            float a[4], bv0, bv1;
            #pragma unroll
            for (int i = 0; i < 4; i++) a[i] = sD[(ty + i*8)*N_ + c*64 + kk];
            bv0 = sKV[kk*65 + tx];
            bv1 = sKV[kk*65 + tx + 32];
            #pragma unroll
            for (int i = 0; i < 4; i++) { oacc[i][0] += a[i]*bv0; oacc[i][1] += a[i]*bv1; }
        }
        __syncthreads();
    }
    #pragma unroll
    for (int i = 0; i < 4; i++) {
        int rg = row0 + ty + i*8;
        float* dst = g_att + ((size_t)bb*N_ + rg)*INNER_ + hh*DH_;
        dst[tx]      = oacc[i][0];
        dst[tx + 32] = oacc[i][1];
    }
}

// ---------------- kernel 3: out = g_att @ W_out + b_out ---------------------
__global__ void out_gemm(const float* __restrict__ Wout,
                         const float* __restrict__ bout,
                         float* __restrict__ out) {
    __shared__ float sA[16][64];
    __shared__ float sB[16][64];
    const int tid = threadIdx.x;
    const int m0 = blockIdx.y * 64;
    const int n0 = blockIdx.x * 64;
    const int ty = tid >> 4, tx = tid & 15;

    float acc[4][4] = {};
    const int arow = tid >> 2, akv = (tid & 3) * 4;
    const int brow = tid >> 4, bcol = (tid & 15) * 4;

    for (int k0 = 0; k0 < INNER_; k0 += 16) {
        float4 av = *(const float4*)(g_att + (size_t)(m0 + arow) * INNER_ + k0 + akv);
        sA[akv+0][arow] = av.x; sA[akv+1][arow] = av.y;
        sA[akv+2][arow] = av.z; sA[akv+3][arow] = av.w;
        float4 bv = *(const float4*)(Wout + (size_t)(k0 + brow) * DIM_ + n0 + bcol);
        *(float4*)&sB[brow][bcol] = bv;
        __syncthreads();
        #pragma unroll
        for (int kk = 0; kk < 16; kk++) {
            float a[4], b[4];
            #pragma unroll
            for (int i = 0; i < 4; i++) a[i] = sA[kk][ty*4+i];
            #pragma unroll
            for (int j = 0; j < 4; j++) b[j] = sB[kk][tx*4+j];
            #pragma unroll
            for (int i = 0; i < 4; i++)
                #pragma unroll
                for (int j = 0; j < 4; j++) acc[i][j] += a[i]*b[j];
        }
        __syncthreads();
    }
    #pragma unroll
    for (int i = 0; i < 4; i++) {
        int mg = m0 + ty*4 + i;
        #pragma unroll
        for (int j = 0; j < 4; j++) {
            int cg = n0 + tx*4 + j;
            out[(size_t)mg*DIM_ + cg] = acc[i][j] + bout[cg];
        }
    }
}

// ---------------- launch -----------------------------------------------------
extern "C" void kernel_launch(void* const* d_in, const int* in_sizes, int n_in,
                              void* d_out, int out_size) {
    const float* x         = (const float*)d_in[0];
    const float* spd       = (const float*)d_in[1];
    const float* head_mask = (const float*)d_in[2];
    const float* W_qkv     = (const float*)d_in[3];
    const float* W_out     = (const float*)d_in[4];
    const float* b_out     = (const float*)d_in[5];
    float* out = (float*)d_out;

    // 1) qkv projection + head split
    qkv_gemm<<<dim3((3*INNER_)/64, (B_*N_)/64), 256>>>(x, W_qkv);

    // 2) fused attention
    size_t smem_bytes = (size_t)(MT_*DH_ + 64*65 + MT_*N_) * sizeof(float); // 155,904 B
    cudaFuncSetAttribute(attn_kernel, cudaFuncAttributeMaxDynamicSharedMemorySize,
                         (int)smem_bytes);
    attn_kernel<<<dim3(N_/MT_, H_, B_), 256, smem_bytes>>>(spd, head_mask);

    // 3) output projection
    out_gemm<<<dim3(DIM_/64, (B_*N_)/64), 256>>>(W_out, b_out, out);
}

// round 3
// speedup vs baseline: 1.4693x; 1.4693x over previous
#include <cuda_runtime.h>
#include <cuda_bf16.h>
#include <math.h>
#include <stdint.h>

#define B_     8
#define N_     1024
#define DIM_   512
#define H_     8
#define DH_    64
#define INNER_ 512
#define MROWS  (B_*N_)          /* 8192 */
#define SCALE_ 0.125f
#define EPS_   1e-12f
#define SD_STRIDE 1032          /* f32 words per dots row (1024 + 8 pad) */

// ---------------- scratch (bf16 split hi/lo everywhere) ---------------------
__device__ __nv_bfloat16 g_xhi[MROWS*DIM_],     g_xlo[MROWS*DIM_];
__device__ __nv_bfloat16 g_w1hi[3*INNER_*DIM_], g_w1lo[3*INNER_*DIM_];  // W_qkv^T [n][k]
__device__ __nv_bfloat16 g_w2hi[DIM_*INNER_],   g_w2lo[DIM_*INNER_];    // W_out^T [n][k]
__device__ __nv_bfloat16 g_qhi[B_*H_*N_*DH_],   g_qlo[B_*H_*N_*DH_];    // [b,h,n,dh]
__device__ __nv_bfloat16 g_khi[B_*H_*N_*DH_],   g_klo[B_*H_*N_*DH_];    // [b,h,n,dh]
__device__ __nv_bfloat16 g_vthi[B_*H_*DH_*N_],  g_vtlo[B_*H_*DH_*N_];   // [b,h,dh,n] (V^T)
__device__ __nv_bfloat16 g_ahi[MROWS*INNER_],   g_alo[MROWS*INNER_];    // attn out [m][inner]

// ---------------- helpers ----------------------------------------------------
__device__ __forceinline__ void mma_bf16(float* c, const uint32_t* a, uint32_t b0, uint32_t b1) {
    asm volatile("mma.sync.aligned.m16n8k16.row.col.f32.bf16.bf16.f32 "
        "{%0,%1,%2,%3}, {%4,%5,%6,%7}, {%8,%9}, {%0,%1,%2,%3};"
        : "+f"(c[0]), "+f"(c[1]), "+f"(c[2]), "+f"(c[3])
        : "r"(a[0]), "r"(a[1]), "r"(a[2]), "r"(a[3]), "r"(b0), "r"(b1));
}

// pack (x=even k, y=odd k) into bf16x2 hi word + exact-residual lo word
__device__ __forceinline__ void split2(float x, float y, uint32_t& h, uint32_t& l) {
    uint32_t hh;
    asm("cvt.rn.bf16x2.f32 %0, %1, %2;" : "=r"(hh) : "f"(y), "f"(x));
    float hx = __uint_as_float(hh << 16);
    float hy = __uint_as_float(hh & 0xFFFF0000u);
    float rx = x - hx, ry = y - hy;
    uint32_t ll;
    asm("cvt.rn.bf16x2.f32 %0, %1, %2;" : "=r"(ll) : "f"(ry), "f"(rx));
    h = hh; l = ll;
}

__device__ __forceinline__ void split1(float x, __nv_bfloat16& h, __nv_bfloat16& l) {
    h = __float2bfloat16_rn(x);
    l = __float2bfloat16_rn(x - __bfloat162float(h));
}

// ---------------- conversion kernels -----------------------------------------
__global__ void k_split_x(const float* __restrict__ in) {
    int i = blockIdx.x*256 + threadIdx.x;
    if (i < MROWS*DIM_) split1(in[i], g_xhi[i], g_xlo[i]);
}
__global__ void k_split_w1(const float* __restrict__ in) {     // [512][1536] -> T
    int o = blockIdx.x*256 + threadIdx.x;
    if (o < 3*INNER_*DIM_) {
        int k = o & 511, n = o >> 9;
        split1(in[(size_t)k*(3*INNER_) + n], g_w1hi[o], g_w1lo[o]);
    }
}
__global__ void k_split_w2(const float* __restrict__ in) {     // [512][512] -> T
    int o = blockIdx.x*256 + threadIdx.x;
    if (o < DIM_*INNER_) {
        int k = o & 511, n = o >> 9;
        split1(in[(size_t)k*DIM_ + n], g_w2hi[o], g_w2lo[o]);
    }
}

// ---------------- warp GEMM core: 64x32 C tile, K=512 ------------------------
// A [M][512] bf16 row-major (hi/lo), Bt [N][512] bf16 row-major (hi/lo).
// rows are 256 x b32 words.
__device__ __forceinline__ void gemm_warp_64x32(
    const uint32_t* __restrict__ Ahi, const uint32_t* __restrict__ Alo,
    const uint32_t* __restrict__ Bhi, const uint32_t* __restrict__ Blo,
    int m_base, int n_base, int g, int tig, float c[4][4][4])
{
    #pragma unroll 2
    for (int ks = 0; ks < 32; ks++) {
        uint32_t bh[4][2], bl[4][2];
        #pragma unroll
        for (int nt = 0; nt < 4; nt++) {
            const uint32_t* ph = Bhi + (size_t)(n_base + nt*8 + g)*256 + ks*8 + tig;
            const uint32_t* pl = Blo + (size_t)(n_base + nt*8 + g)*256 + ks*8 + tig;
            bh[nt][0] = ph[0]; bh[nt][1] = ph[4];
            bl[nt][0] = pl[0]; bl[nt][1] = pl[4];
        }
        #pragma unroll
        for (int mt = 0; mt < 4; mt++) {
            const uint32_t* ph = Ahi + (size_t)(m_base + mt*16 + g)*256 + ks*8 + tig;
            const uint32_t* pl = Alo + (size_t)(m_base + mt*16 + g)*256 + ks*8 + tig;
            uint32_t ah[4] = { ph[0], ph[8*256], ph[4], ph[8*256+4] };
            uint32_t al[4] = { pl[0], pl[8*256], pl[4], pl[8*256+4] };
            #pragma unroll
            for (int nt = 0; nt < 4; nt++) {
                mma_bf16(c[mt][nt], ah, bh[nt][0], bh[nt][1]);
                mma_bf16(c[mt][nt], ah, bl[nt][0], bl[nt][1]);
                mma_bf16(c[mt][nt], al, bh[nt][0], bh[nt][1]);
            }
        }
    }
}

// ---------------- kernel 1: qkv projection -----------------------------------
__global__ void __launch_bounds__(256) qkv_mma() {
    const int tid = threadIdx.x, w = tid >> 5, lane = tid & 31;
    const int g = lane >> 2, tig = lane & 3;
    const int m0 = blockIdx.y*128 + (w >> 2)*64;
    const int n0 = blockIdx.x*128 + (w & 3)*32;

    float c[4][4][4] = {};
    gemm_warp_64x32((const uint32_t*)g_xhi, (const uint32_t*)g_xlo,
                    (const uint32_t*)g_w1hi, (const uint32_t*)g_w1lo,
                    m0, n0, g, tig, c);

    #pragma unroll
    for (int mt = 0; mt < 4; mt++)
    #pragma unroll
    for (int nt = 0; nt < 4; nt++)
    #pragma unroll
    for (int half = 0; half < 2; half++) {
        int mg = m0 + mt*16 + g + half*8;
        int bb = mg >> 10, nn = mg & 1023;
        int ng = n0 + nt*8 + 2*tig;
        int sec = ng >> 9;             // /512
        int cc  = ng & 511;
        int hh  = cc >> 6, dd = cc & 63;
        float xv = c[mt][nt][half*2], yv = c[mt][nt][half*2+1];
        if (sec < 2) {
            uint32_t h, l; split2(xv, yv, h, l);
            size_t widx = ((((size_t)bb*H_ + hh)*N_ + nn)*DH_ + dd) >> 1;
            if (sec == 0) { ((uint32_t*)g_qhi)[widx] = h; ((uint32_t*)g_qlo)[widx] = l; }
            else          { ((uint32_t*)g_khi)[widx] = h; ((uint32_t*)g_klo)[widx] = l; }
        } else {
            __nv_bfloat16 h0,l0,h1,l1; split1(xv,h0,l0); split1(yv,h1,l1);
            size_t vb = (((size_t)bb*H_ + hh)*DH_ + dd)*N_ + nn;
            g_vthi[vb]      = h0; g_vtlo[vb]      = l0;
            g_vthi[vb + N_] = h1; g_vtlo[vb + N_] = l1;
        }
    }
}

// ---------------- kernel 2: fused attention ----------------------------------
__global__ void __launch_bounds__(256) attn_mma(const float* __restrict__ spd,
                                                const float* __restrict__ head_mask) {
    extern __shared__ float sD[];      // 32 rows x SD_STRIDE f32
    const int tid = threadIdx.x, w = tid >> 5, lane = tid & 31;
    const int g = lane >> 2, tig = lane & 3;
    const int bb = blockIdx.z, hh = blockIdx.y, row0 = blockIdx.x*32;
    const int mw = w & 1, nw = w >> 1;
    const int mrow = mw*16 + g;

    const uint32_t* Qhi = (const uint32_t*)g_qhi + ((size_t)(bb*H_+hh)*N_ + row0)*(DH_/2);
    const uint32_t* Qlo = (const uint32_t*)g_qlo + ((size_t)(bb*H_+hh)*N_ + row0)*(DH_/2);
    const uint32_t* Khi = (const uint32_t*)g_khi + (size_t)(bb*H_+hh)*N_*(DH_/2);
    const uint32_t* Klo = (const uint32_t*)g_klo + (size_t)(bb*H_+hh)*N_*(DH_/2);

    // ---- phase 1: dots = (Q K^T) * SCALE into sD (f32) ----
    uint32_t ah[4][4], al[4][4];
    {
        const uint32_t* ph = Qhi + (size_t)mrow*32;
        const uint32_t* pl = Qlo + (size_t)mrow*32;
        #pragma unroll
        for (int ks = 0; ks < 4; ks++) {
            ah[ks][0]=ph[ks*8+tig];   ah[ks][1]=ph[8*32+ks*8+tig];
            ah[ks][2]=ph[ks*8+tig+4]; ah[ks][3]=ph[8*32+ks*8+tig+4];
            al[ks][0]=pl[ks*8+tig];   al[ks][1]=pl[8*32+ks*8+tig];
            al[ks][2]=pl[ks*8+tig+4]; al[ks][3]=pl[8*32+ks*8+tig+4];
        }
    }
    for (int nt = 0; nt < 32; nt++) {
        const int n0 = nw*256 + nt*8;
        float c[4] = {0.f,0.f,0.f,0.f};
        #pragma unroll
        for (int ks = 0; ks < 4; ks++) {
            const uint32_t* ph = Khi + (size_t)(n0+g)*32 + ks*8 + tig;
            const uint32_t* pl = Klo + (size_t)(n0+g)*32 + ks*8 + tig;
            uint32_t bh0 = ph[0], bh1 = ph[4], bl0 = pl[0], bl1 = pl[4];
            mma_bf16(c, ah[ks], bh0, bh1);
            mma_bf16(c, ah[ks], bl0, bl1);
            mma_bf16(c, al[ks], bh0, bh1);
        }
        float2 v0 = { c[0]*SCALE_, c[1]*SCALE_ };
        float2 v1 = { c[2]*SCALE_, c[3]*SCALE_ };
        *(float2*)&sD[(size_t)mrow*SD_STRIDE + n0 + 2*tig]     = v0;
        *(float2*)&sD[(size_t)(mrow+8)*SD_STRIDE + n0 + 2*tig] = v1;
    }
    __syncthreads();

    // ---- phase 2: bias + softmax + head-mask rescale; split to bf16 in place ----
    float msum = 0.f;
    #pragma unroll
    for (int i = 0; i < H_; i++) msum += head_mask[i];
    const float scale_m = head_mask[hh] * (float)H_ / msum;

    for (int rr = 0; rr < 4; rr++) {
        const int r = w*4 + rr, rg = row0 + r;
        float* drow = sD + (size_t)r*SD_STRIDE;
        const float* srow = spd + ((size_t)bb*N_ + rg)*N_;

        float accd = 0.f, accp = 0.f;
        for (int j = lane; j < N_; j += 32) {
            float d = drow[j], p = d*srow[j];
            accd += d*d; accp += p*p;
        }
        #pragma unroll
        for (int o = 16; o > 0; o >>= 1) {
            accd += __shfl_xor_sync(0xffffffffu, accd, o);
            accp += __shfl_xor_sync(0xffffffffu, accp, o);
        }
        const float rnorm = sqrtf(accd) / fmaxf(sqrtf(accp), EPS_);

        float mx = -INFINITY;
        for (int j = lane; j < N_; j += 32) {
            float d = drow[j];
            float t = d + d*srow[j]*rnorm;
            drow[j] = t;
            mx = fmaxf(mx, t);
        }
        #pragma unroll
        for (int o = 16; o > 0; o >>= 1) mx = fmaxf(mx, __shfl_xor_sync(0xffffffffu, mx, o));

        float s = 0.f;
        for (int j = lane; j < N_; j += 32) {
            float e = __expf(drow[j] - mx);
            drow[j] = e;
            s += e;
        }
        #pragma unroll
        for (int o = 16; o > 0; o >>= 1) s += __shfl_xor_sync(0xffffffffu, s, o);

        const float inv = scale_m / s;

        // stage row into regs, then overwrite row region with bf16 hi(0..2KB)/lo(2..4KB)
        __syncwarp();
        float vb[32];
        #pragma unroll
        for (int i = 0; i < 16; i++) {
            float2 p = *(float2*)&drow[2*lane + 64*i];
            vb[2*i] = p.x*inv; vb[2*i+1] = p.y*inv;
        }
        __syncwarp();
        char* rb = (char*)drow;
        #pragma unroll
        for (int i = 0; i < 16; i++) {
            uint32_t h, l; split2(vb[2*i], vb[2*i+1], h, l);
            *(uint32_t*)(rb + 4*lane + 128*i)        = h;
            *(uint32_t*)(rb + 2048 + 4*lane + 128*i) = l;
        }
    }
    __syncthreads();

    // ---- phase 3: O = attn @ V  (A: bf16 split in smem, B: V^T from global) ----
    const uint32_t* Vhi = (const uint32_t*)g_vthi + (size_t)(bb*H_+hh)*DH_*(N_/2);
    const uint32_t* Vlo = (const uint32_t*)g_vtlo + (size_t)(bb*H_+hh)*DH_*(N_/2);
    const int dh0 = nw*16;
    float oc[2][4] = {};
    const char* rb0 = (const char*)(sD + (size_t)mrow*SD_STRIDE);
    const char* rb1 = (const char*)(sD + (size_t)(mrow+8)*SD_STRIDE);

    #pragma unroll 2
    for (int ks = 0; ks < 64; ks++) {
        const int off = ks*32 + 4*tig;
        uint32_t a4h[4] = { *(const uint32_t*)(rb0+off),    *(const uint32_t*)(rb1+off),
                            *(const uint32_t*)(rb0+off+16), *(const uint32_t*)(rb1+off+16) };
        uint32_t a4l[4] = { *(const uint32_t*)(rb0+2048+off),    *(const uint32_t*)(rb1+2048+off),
                            *(const uint32_t*)(rb0+2048+off+16), *(const uint32_t*)(rb1+2048+off+16) };
        #pragma unroll
        for (int nt = 0; nt < 2; nt++) {
            const uint32_t* ph = Vhi + (size_t)(dh0 + nt*8 + g)*(N_/2) + ks*8 + tig;
            const uint32_t* pl = Vlo + (size_t)(dh0 + nt*8 + g)*(N_/2) + ks*8 + tig;
            uint32_t bh0 = ph[0], bh1 = ph[4], bl0 = pl[0], bl1 = pl[4];
            mma_bf16(oc[nt], a4h, bh0, bh1);
            mma_bf16(oc[nt], a4h, bl0, bl1);
            mma_bf16(oc[nt], a4l, bh0, bh1);
        }
    }

    #pragma unroll
    for (int nt = 0; nt < 2; nt++)
    #pragma unroll
    for (int half = 0; half < 2; half++) {
        int rg  = row0 + mw*16 + g + half*8;
        size_t mg = (size_t)bb*N_ + rg;                 // FIX: global row incl. batch
        int col = hh*64 + dh0 + nt*8 + 2*tig;
        uint32_t h, l; split2(oc[nt][half*2], oc[nt][half*2+1], h, l);
        size_t widx = (mg*INNER_ + col) >> 1;
        ((uint32_t*)g_ahi)[widx] = h; ((uint32_t*)g_alo)[widx] = l;
    }
}

// ---------------- kernel 3: output projection --------------------------------
__global__ void __launch_bounds__(256) out_mma(const float* __restrict__ bout,
                                               float* __restrict__ out) {
    const int tid = threadIdx.x, w = tid >> 5, lane = tid & 31;
    const int g = lane >> 2, tig = lane & 3;
    const int m0 = blockIdx.y*128 + (w >> 2)*64;
    const int n0 = blockIdx.x*128 + (w & 3)*32;

    float c[4][4][4] = {};
    gemm_warp_64x32((const uint32_t*)g_ahi, (const uint32_t*)g_alo,
                    (const uint32_t*)g_w2hi, (const uint32_t*)g_w2lo,
                    m0, n0, g, tig, c);

    #pragma unroll
    for (int mt = 0; mt < 4; mt++)
    #pragma unroll
    for (int nt = 0; nt < 4; nt++)
    #pragma unroll
    for (int half = 0; half < 2; half++) {
        int mg = m0 + mt*16 + g + half*8;
        int ng = n0 + nt*8 + 2*tig;
        float2 v = { c[mt][nt][half*2]   + bout[ng],
                     c[mt][nt][half*2+1] + bout[ng+1] };
        *(float2*)(out + (size_t)mg*DIM_ + ng) = v;
    }
}

// ---------------- launch ------------------------------------------------------
extern "C" void kernel_launch(void* const* d_in, const int* in_sizes, int n_in,
                              void* d_out, int out_size) {
    const float* x         = (const float*)d_in[0];
    const float* spd       = (const float*)d_in[1];
    const float* head_mask = (const float*)d_in[2];
    const float* W_qkv     = (const float*)d_in[3];
    const float* W_out     = (const float*)d_in[4];
    const float* b_out     = (const float*)d_in[5];
    float* out = (float*)d_out;

    k_split_x <<<(MROWS*DIM_ + 255)/256, 256>>>(x);
    k_split_w1<<<(3*INNER_*DIM_ + 255)/256, 256>>>(W_qkv);
    k_split_w2<<<(DIM_*INNER_ + 255)/256, 256>>>(W_out);

    qkv_mma<<<dim3(12, 64), 256>>>();

    size_t smem = (size_t)32*SD_STRIDE*sizeof(float);   // 132096 B
    cudaFuncSetAttribute(attn_mma, cudaFuncAttributeMaxDynamicSharedMemorySize, (int)smem);
    attn_mma<<<dim3(N_/32, H_, B_), 256, smem>>>(spd, head_mask);

    out_mma<<<dim3(4, 64), 256>>>(b_out, out);
}

// round 5
// speedup vs baseline: 2.2681x; 1.5437x over previous
#include <cuda_runtime.h>
#include <cuda_bf16.h>
#include <math.h>
#include <stdint.h>

#define B_     8
#define N_     1024
#define DIM_   512
#define H_     8
#define DH_    64
#define INNER_ 512
#define MROWS  (B_*N_)          /* 8192 */
#define SCALE_ 0.125f
#define EPS_   1e-12f
#define SD_STRIDE 1028          /* f32 words per dots row (1024 + 4 pad); 4112B = 257*16 */

// Word permutation within 32-word (64 k-element) blocks:
//   natural o = ks*8 + s*4 + tig   ->   stored p = tig*8 + ks*2 + s
// so each lane's 8 fragment words per 64-k block are contiguous (2x LDG.128).
__device__ __forceinline__ int permw(int o)   { return (o&3)*8 + (o>>3)*2 + ((o>>2)&1); }
__device__ __forceinline__ int invperm(int w) { return ((w>>1)&3)*8 + (w&1)*4 + (w>>3); }

// ---------------- scratch -----------------------------------------------------
__device__ __align__(256) __nv_bfloat16 g_xhi[MROWS*DIM_],     g_xlo[MROWS*DIM_];
__device__ __align__(256) __nv_bfloat16 g_w1hi[3*INNER_*DIM_], g_w1lo[3*INNER_*DIM_]; // W_qkv^T perm
__device__ __align__(256) __nv_bfloat16 g_w2hi[DIM_*INNER_],   g_w2lo[DIM_*INNER_];   // W_out^T perm
__device__ __align__(256) __nv_bfloat16 g_qhi[B_*H_*N_*DH_],   g_qlo[B_*H_*N_*DH_];   // [b,h,n,dh] perm
__device__ __align__(256) __nv_bfloat16 g_khi[B_*H_*N_*DH_],   g_klo[B_*H_*N_*DH_];   // [b,h,n,dh] perm
__device__ __align__(256) __nv_bfloat16 g_vthi[B_*H_*DH_*N_],  g_vtlo[B_*H_*DH_*N_];  // [b,h,dh,n] perm
__device__ __align__(256) __nv_bfloat16 g_ahi[MROWS*INNER_],   g_alo[MROWS*INNER_];   // [m][inner] perm

// ---------------- helpers ------------------------------------------------------
__device__ __forceinline__ void mma_bf16(float* c, const uint32_t* a, uint32_t b0, uint32_t b1) {
    asm volatile("mma.sync.aligned.m16n8k16.row.col.f32.bf16.bf16.f32 "
        "{%0,%1,%2,%3}, {%4,%5,%6,%7}, {%8,%9}, {%0,%1,%2,%3};"
        : "+f"(c[0]), "+f"(c[1]), "+f"(c[2]), "+f"(c[3])
        : "r"(a[0]), "r"(a[1]), "r"(a[2]), "r"(a[3]), "r"(b0), "r"(b1));
}

// pack (x=even k, y=odd k): hi word (x low half) + exact residual lo word
__device__ __forceinline__ void split2(float x, float y, uint32_t& h, uint32_t& l) {
    uint32_t hh;
    asm("cvt.rn.bf16x2.f32 %0, %1, %2;" : "=r"(hh) : "f"(y), "f"(x));
    float hx = __uint_as_float(hh << 16);
    float hy = __uint_as_float(hh & 0xFFFF0000u);
    uint32_t ll;
    asm("cvt.rn.bf16x2.f32 %0, %1, %2;" : "=r"(ll) : "f"(y - hy), "f"(x - hx));
    h = hh; l = ll;
}
__device__ __forceinline__ void split1(float x, __nv_bfloat16& h, __nv_bfloat16& l) {
    h = __float2bfloat16_rn(x);
    l = __float2bfloat16_rn(x - __bfloat162float(h));
}
__device__ __forceinline__ uint32_t pack2(__nv_bfloat16 e0, __nv_bfloat16 e1) {
    return ((uint32_t)__bfloat16_as_ushort(e1) << 16) | __bfloat16_as_ushort(e0);
}

// ---------------- conversion kernels -------------------------------------------
// x [8192][512] -> permuted split rows
__global__ void k_split_x(const float* __restrict__ in) {
    int row = blockIdx.x*8 + (threadIdx.x >> 5);
    int lane = threadIdx.x & 31;
    const float* src = in + (size_t)row*DIM_;
    uint32_t* dh = (uint32_t*)g_xhi + (size_t)row*256;
    uint32_t* dl = (uint32_t*)g_xlo + (size_t)row*256;
    #pragma unroll
    for (int j = 0; j < 8; j++) {
        int p = lane + 32*j;
        int o = (p & ~31) | invperm(p & 31);
        float2 v = *(const float2*)(src + 2*o);
        __nv_bfloat16 h0,l0,h1,l1; split1(v.x,h0,l0); split1(v.y,h1,l1);
        dh[p] = pack2(h0,h1);
        dl[p] = pack2(l0,l1);
    }
}

// W [512 k][W n] -> transposed+permuted split [n][256 words]
__global__ void k_split_w(const float* __restrict__ in, int W,
                          __nv_bfloat16* __restrict__ outh, __nv_bfloat16* __restrict__ outl) {
    __shared__ float s[64][33];
    int n0 = blockIdx.x*32, k0 = blockIdx.y*64;
    int t = threadIdx.x;
    int nn = t & 31, kk = t >> 5;
    #pragma unroll
    for (int i = 0; i < 8; i++)
        s[kk + 8*i][nn] = in[(size_t)(k0 + kk + 8*i)*W + n0 + nn];
    __syncthreads();
    int nl = t >> 3, wg = (t & 7)*4;
    uint32_t* oh = (uint32_t*)outh + (size_t)(n0+nl)*256 + blockIdx.y*32;
    uint32_t* ol = (uint32_t*)outl + (size_t)(n0+nl)*256 + blockIdx.y*32;
    #pragma unroll
    for (int j = 0; j < 4; j++) {
        int w = wg + j;
        int o = invperm(w);
        __nv_bfloat16 h0,l0,h1,l1;
        split1(s[2*o][nl],   h0, l0);
        split1(s[2*o+1][nl], h1, l1);
        oh[w] = pack2(h0,h1);
        ol[w] = pack2(l0,l1);
    }
}

// ---------------- warp GEMM core: 64x32 C tile, K=512, permuted LDG.128 --------
// A/Bt rows = 256 words = 64 uint4 each (hi and lo arrays).
__device__ __forceinline__ void gemm_warp_64x32_p(
    const uint4* __restrict__ Ahi, const uint4* __restrict__ Alo,
    const uint4* __restrict__ Bhi, const uint4* __restrict__ Blo,
    int m_base, int n_base, int g, int tig, float c[4][4][4])
{
    for (int kb = 0; kb < 8; kb++) {
        uint32_t bh[4][8], bl[4][8];
        #pragma unroll
        for (int nt = 0; nt < 4; nt++) {
            const uint4* p = Bhi + (size_t)(n_base + nt*8 + g)*64 + kb*8 + tig*2;
            uint4 f0 = p[0], f1 = p[1];
            bh[nt][0]=f0.x; bh[nt][1]=f0.y; bh[nt][2]=f0.z; bh[nt][3]=f0.w;
            bh[nt][4]=f1.x; bh[nt][5]=f1.y; bh[nt][6]=f1.z; bh[nt][7]=f1.w;
            const uint4* q = Blo + (size_t)(n_base + nt*8 + g)*64 + kb*8 + tig*2;
            uint4 g0 = q[0], g1 = q[1];
            bl[nt][0]=g0.x; bl[nt][1]=g0.y; bl[nt][2]=g0.z; bl[nt][3]=g0.w;
            bl[nt][4]=g1.x; bl[nt][5]=g1.y; bl[nt][6]=g1.z; bl[nt][7]=g1.w;
        }
        #pragma unroll
        for (int mt = 0; mt < 4; mt++) {
            const uint4* pr = Ahi + (size_t)(m_base + mt*16 + g)*64 + kb*8 + tig*2;
            uint4 F0 = pr[0],     F1 = pr[1];
            uint4 S0 = pr[8*64],  S1 = pr[8*64 + 1];
            const uint4* ql = Alo + (size_t)(m_base + mt*16 + g)*64 + kb*8 + tig*2;
            uint4 G0 = ql[0],     G1 = ql[1];
            uint4 T0 = ql[8*64],  T1 = ql[8*64 + 1];
            uint32_t ah[4][4] = {
                {F0.x,S0.x,F0.y,S0.y},{F0.z,S0.z,F0.w,S0.w},
                {F1.x,S1.x,F1.y,S1.y},{F1.z,S1.z,F1.w,S1.w}};
            uint32_t al[4][4] = {
                {G0.x,T0.x,G0.y,T0.y},{G0.z,T0.z,G0.w,T0.w},
                {G1.x,T1.x,G1.y,T1.y},{G1.z,T1.z,G1.w,T1.w}};
            #pragma unroll
            for (int ks = 0; ks < 4; ks++)
                #pragma unroll
                for (int nt = 0; nt < 4; nt++) {
                    mma_bf16(c[mt][nt], ah[ks], bh[nt][ks*2], bh[nt][ks*2+1]);
                    mma_bf16(c[mt][nt], ah[ks], bl[nt][ks*2], bl[nt][ks*2+1]);
                    mma_bf16(c[mt][nt], al[ks], bh[nt][ks*2], bh[nt][ks*2+1]);
                }
        }
    }
}

// ---------------- kernel 1: qkv projection -------------------------------------
__global__ void __launch_bounds__(256) qkv_mma() {
    const int tid = threadIdx.x, w = tid >> 5, lane = tid & 31;
    const int g = lane >> 2, tig = lane & 3;
    const int m0 = blockIdx.y*128 + (w >> 2)*64;
    const int n0 = blockIdx.x*128 + (w & 3)*32;

    float c[4][4][4] = {};
    gemm_warp_64x32_p((const uint4*)g_xhi, (const uint4*)g_xlo,
                      (const uint4*)g_w1hi, (const uint4*)g_w1lo,
                      m0, n0, g, tig, c);

    #pragma unroll
    for (int mt = 0; mt < 4; mt++)
    #pragma unroll
    for (int nt = 0; nt < 4; nt++)
    #pragma unroll
    for (int half = 0; half < 2; half++) {
        int mg = m0 + mt*16 + g + half*8;
        int bb = mg >> 10, nn = mg & 1023;
        int ng = n0 + nt*8 + 2*tig;
        int sec = ng >> 9;
        int cc  = ng & 511;
        int hh  = cc >> 6, dd = cc & 63;
        float xv = c[mt][nt][half*2], yv = c[mt][nt][half*2+1];
        if (sec < 2) {
            uint32_t h, l; split2(xv, yv, h, l);
            int pw = permw(dd >> 1);
            size_t widx = (((size_t)bb*H_ + hh)*N_ + nn)*32 + pw;
            if (sec == 0) { ((uint32_t*)g_qhi)[widx] = h; ((uint32_t*)g_qlo)[widx] = l; }
            else          { ((uint32_t*)g_khi)[widx] = h; ((uint32_t*)g_klo)[widx] = l; }
        } else {
            __nv_bfloat16 h0,l0,h1,l1; split1(xv,h0,l0); split1(yv,h1,l1);
            int o = nn >> 1, hb = nn & 1;
            int pe = ((o & ~31) | permw(o & 31))*2 + hb;
            size_t base = (((size_t)bb*H_ + hh)*DH_ + dd)*N_;
            g_vthi[base + pe] = h0;       g_vtlo[base + pe] = l0;
            g_vthi[base + N_ + pe] = h1;  g_vtlo[base + N_ + pe] = l1;   // row dd+1
        }
    }
}

// ---------------- kernel 2: fused attention ------------------------------------
__global__ void __launch_bounds__(256) attn_mma(const float* __restrict__ spd,
                                                const float* __restrict__ head_mask) {
    extern __shared__ float sD[];      // 32 rows x SD_STRIDE f32
    const int tid = threadIdx.x, w = tid >> 5, lane = tid & 31;
    const int g = lane >> 2, tig = lane & 3;
    const int bb = blockIdx.z, hh = blockIdx.y, row0 = blockIdx.x*32;
    const int mw = w & 1, nw = w >> 1;
    const int mrow = mw*16 + g;

    const uint4* Khi4 = (const uint4*)g_khi + (size_t)(bb*H_+hh)*N_*8;
    const uint4* Klo4 = (const uint4*)g_klo + (size_t)(bb*H_+hh)*N_*8;

    // ---- phase 1: dots = (Q K^T) * SCALE into sD (f32) ----
    uint32_t ah[4][4], al[4][4];
    {
        const uint4* qh = (const uint4*)g_qhi + ((size_t)(bb*H_+hh)*N_ + row0 + mrow)*8 + tig*2;
        const uint4* ql = (const uint4*)g_qlo + ((size_t)(bb*H_+hh)*N_ + row0 + mrow)*8 + tig*2;
        uint4 F0 = qh[0],    F1 = qh[1];
        uint4 S0 = qh[8*8],  S1 = qh[8*8+1];
        uint4 G0 = ql[0],    G1 = ql[1];
        uint4 T0 = ql[8*8],  T1 = ql[8*8+1];
        ah[0][0]=F0.x; ah[0][1]=S0.x; ah[0][2]=F0.y; ah[0][3]=S0.y;
        ah[1][0]=F0.z; ah[1][1]=S0.z; ah[1][2]=F0.w; ah[1][3]=S0.w;
        ah[2][0]=F1.x; ah[2][1]=S1.x; ah[2][2]=F1.y; ah[2][3]=S1.y;
        ah[3][0]=F1.z; ah[3][1]=S1.z; ah[3][2]=F1.w; ah[3][3]=S1.w;
        al[0][0]=G0.x; al[0][1]=T0.x; al[0][2]=G0.y; al[0][3]=T0.y;
        al[1][0]=G0.z; al[1][1]=T0.z; al[1][2]=G0.w; al[1][3]=T0.w;
        al[2][0]=G1.x; al[2][1]=T1.x; al[2][2]=G1.y; al[2][3]=T1.y;
        al[3][0]=G1.z; al[3][1]=T1.z; al[3][2]=G1.w; al[3][3]=T1.w;
    }
    for (int nt = 0; nt < 32; nt++) {
        const int n0 = nw*256 + nt*8;
        const uint4* ph = Khi4 + (size_t)(n0+g)*8 + tig*2;
        const uint4* pl = Klo4 + (size_t)(n0+g)*8 + tig*2;
        uint4 F0 = ph[0], F1 = ph[1];
        uint4 G0 = pl[0], G1 = pl[1];
        uint32_t bhw[8] = {F0.x,F0.y,F0.z,F0.w,F1.x,F1.y,F1.z,F1.w};
        uint32_t blw[8] = {G0.x,G0.y,G0.z,G0.w,G1.x,G1.y,G1.z,G1.w};
        float c[4] = {0.f,0.f,0.f,0.f};
        #pragma unroll
        for (int ks = 0; ks < 4; ks++) {
            mma_bf16(c, ah[ks], bhw[ks*2], bhw[ks*2+1]);
            mma_bf16(c, ah[ks], blw[ks*2], blw[ks*2+1]);
            mma_bf16(c, al[ks], bhw[ks*2], bhw[ks*2+1]);
        }
        float2 v0 = { c[0]*SCALE_, c[1]*SCALE_ };
        float2 v1 = { c[2]*SCALE_, c[3]*SCALE_ };
        *(float2*)&sD[(size_t)mrow*SD_STRIDE + n0 + 2*tig]     = v0;
        *(float2*)&sD[(size_t)(mrow+8)*SD_STRIDE + n0 + 2*tig] = v1;
    }
    __syncthreads();

    // ---- phase 2: bias + softmax + head-mask rescale; permuted bf16 in place ----
    float msum = 0.f;
    #pragma unroll
    for (int i = 0; i < H_; i++) msum += head_mask[i];
    const float scale_m = head_mask[hh] * (float)H_ / msum;
    const int pl = permw(lane);

    for (int rr = 0; rr < 4; rr++) {
        const int r = w*4 + rr, rg = row0 + r;
        float* drow = sD + (size_t)r*SD_STRIDE;
        const float* srow = spd + ((size_t)bb*N_ + rg)*N_;

        float accd = 0.f, accp = 0.f;
        for (int j = lane; j < N_; j += 32) {
            float d = drow[j], p = d*srow[j];
            accd += d*d; accp += p*p;
        }
        #pragma unroll
        for (int o = 16; o > 0; o >>= 1) {
            accd += __shfl_xor_sync(0xffffffffu, accd, o);
            accp += __shfl_xor_sync(0xffffffffu, accp, o);
        }
        const float rnorm = sqrtf(accd) / fmaxf(sqrtf(accp), EPS_);

        float mx = -INFINITY;
        for (int j = lane; j < N_; j += 32) {
            float d = drow[j];
            float t = d + d*srow[j]*rnorm;
            drow[j] = t;
            mx = fmaxf(mx, t);
        }
        #pragma unroll
        for (int o = 16; o > 0; o >>= 1) mx = fmaxf(mx, __shfl_xor_sync(0xffffffffu, mx, o));

        float s = 0.f;
        for (int j = lane; j < N_; j += 32) {
            float e = __expf(drow[j] - mx);
            drow[j] = e;
            s += e;
        }
        #pragma unroll
        for (int o = 16; o > 0; o >>= 1) s += __shfl_xor_sync(0xffffffffu, s, o);

        const float inv = scale_m / s;

        // FIX: stage NATURAL word (32i + lane) = elements (64i + 2*lane, +1),
        // then write it to STORED position (32i + permw(lane)).
        __syncwarp();
        float vb[32];
        #pragma unroll
        for (int i = 0; i < 16; i++) {
            float2 p = *(float2*)&drow[2*lane + 64*i];
            vb[2*i] = p.x*inv; vb[2*i+1] = p.y*inv;
        }
        __syncwarp();
        uint32_t* dw = (uint32_t*)drow;
        #pragma unroll
        for (int i = 0; i < 16; i++) {
            uint32_t h, l; split2(vb[2*i], vb[2*i+1], h, l);
            dw[i*32 + pl]       = h;
            dw[512 + i*32 + pl] = l;
        }
    }
    __syncthreads();

    // ---- phase 3: O = attn @ V  (A: permuted bf16 in smem, B: permuted V^T) ----
    const uint4* Vhi4 = (const uint4*)g_vthi + (size_t)(bb*H_+hh)*DH_*128;
    const uint4* Vlo4 = (const uint4*)g_vtlo + (size_t)(bb*H_+hh)*DH_*128;
    const int dh0 = nw*16;
    float oc[2][4] = {};
    const uint4* r0 = (const uint4*)(sD + (size_t)mrow*SD_STRIDE);
    const uint4* r1 = (const uint4*)(sD + (size_t)(mrow+8)*SD_STRIDE);

    for (int kb = 0; kb < 16; kb++) {
        const int ob = kb*8 + tig*2;
        uint4 F0 = r0[ob],       F1 = r0[ob+1];
        uint4 H0 = r1[ob],       H1 = r1[ob+1];
        uint4 G0 = r0[128+ob],   G1 = r0[128+ob+1];
        uint4 T0 = r1[128+ob],   T1 = r1[128+ob+1];
        uint32_t a4h[4][4] = {
            {F0.x,H0.x,F0.y,H0.y},{F0.z,H0.z,F0.w,H0.w},
            {F1.x,H1.x,F1.y,H1.y},{F1.z,H1.z,F1.w,H1.w}};
        uint32_t a4l[4][4] = {
            {G0.x,T0.x,G0.y,T0.y},{G0.z,T0.z,G0.w,T0.w},
            {G1.x,T1.x,G1.y,T1.y},{G1.z,T1.z,G1.w,T1.w}};
        #pragma unroll
        for (int nt = 0; nt < 2; nt++) {
            const uint4* ph = Vhi4 + (size_t)(dh0 + nt*8 + g)*128 + ob;
            const uint4* pv = Vlo4 + (size_t)(dh0 + nt*8 + g)*128 + ob;
            uint4 P0 = ph[0], P1 = ph[1];
            uint4 Q0 = pv[0], Q1 = pv[1];
            uint32_t bhw[8] = {P0.x,P0.y,P0.z,P0.w,P1.x,P1.y,P1.z,P1.w};
            uint32_t blw[8] = {Q0.x,Q0.y,Q0.z,Q0.w,Q1.x,Q1.y,Q1.z,Q1.w};
            #pragma unroll
            for (int ks = 0; ks < 4; ks++) {
                mma_bf16(oc[nt], a4h[ks], bhw[ks*2], bhw[ks*2+1]);
                mma_bf16(oc[nt], a4h[ks], blw[ks*2], blw[ks*2+1]);
                mma_bf16(oc[nt], a4l[ks], bhw[ks*2], bhw[ks*2+1]);
            }
        }
    }

    #pragma unroll
    for (int nt = 0; nt < 2; nt++)
    #pragma unroll
    for (int half = 0; half < 2; half++) {
        int rg  = row0 + mw*16 + g + half*8;
        size_t mg = (size_t)bb*N_ + rg;
        int rcol = dh0 + nt*8 + 2*tig;              // 0..62 within head
        uint32_t h, l; split2(oc[nt][half*2], oc[nt][half*2+1], h, l);
        int pw = hh*32 + permw(rcol >> 1);
        size_t widx = mg*256 + pw;
        ((uint32_t*)g_ahi)[widx] = h; ((uint32_t*)g_alo)[widx] = l;
    }
}

// ---------------- kernel 3: output projection ----------------------------------
__global__ void __launch_bounds__(256) out_mma(const float* __restrict__ bout,
                                               float* __restrict__ out) {
    const int tid = threadIdx.x, w = tid >> 5, lane = tid & 31;
    const int g = lane >> 2, tig = lane & 3;
    const int m0 = blockIdx.y*128 + (w >> 2)*64;
    const int n0 = blockIdx.x*128 + (w & 3)*32;

    float c[4][4][4] = {};
    gemm_warp_64x32_p((const uint4*)g_ahi, (const uint4*)g_alo,
                      (const uint4*)g_w2hi, (const uint4*)g_w2lo,
                      m0, n0, g, tig, c);

    #pragma unroll
    for (int mt = 0; mt < 4; mt++)
    #pragma unroll
    for (int nt = 0; nt < 4; nt++)
    #pragma unroll
    for (int half = 0; half < 2; half++) {
        int mg = m0 + mt*16 + g + half*8;
        int ng = n0 + nt*8 + 2*tig;
        float2 v = { c[mt][nt][half*2]   + bout[ng],
                     c[mt][nt][half*2+1] + bout[ng+1] };
        *(float2*)(out + (size_t)mg*DIM_ + ng) = v;
    }
}

// ---------------- launch ---------------------------------------------------------
extern "C" void kernel_launch(void* const* d_in, const int* in_sizes, int n_in,
                              void* d_out, int out_size) {
    const float* x         = (const float*)d_in[0];
    const float* spd       = (const float*)d_in[1];
    const float* head_mask = (const float*)d_in[2];
    const float* W_qkv     = (const float*)d_in[3];
    const float* W_out     = (const float*)d_in[4];
    const float* b_out     = (const float*)d_in[5];
    float* out = (float*)d_out;

    __nv_bfloat16 *w1h, *w1l, *w2h, *w2l;
    cudaGetSymbolAddress((void**)&w1h, g_w1hi); cudaGetSymbolAddress((void**)&w1l, g_w1lo);
    cudaGetSymbolAddress((void**)&w2h, g_w2hi); cudaGetSymbolAddress((void**)&w2l, g_w2lo);

    k_split_x<<<MROWS/8, 256>>>(x);
    k_split_w<<<dim3(48, 8), 256>>>(W_qkv, 3*INNER_, w1h, w1l);
    k_split_w<<<dim3(16, 8), 256>>>(W_out, DIM_,     w2h, w2l);

    qkv_mma<<<dim3(12, 64), 256>>>();

    size_t smem = (size_t)32*SD_STRIDE*sizeof(float);   // 131584 B
    cudaFuncSetAttribute(attn_mma, cudaFuncAttributeMaxDynamicSharedMemorySize, (int)smem);
    attn_mma<<<dim3(N_/32, H_, B_), 256, smem>>>(spd, head_mask);

    out_mma<<<dim3(4, 64), 256>>>(b_out, out);
}

// round 6
// speedup vs baseline: 3.3323x; 1.4692x over previous
#include <cuda_runtime.h>
#include <cuda_bf16.h>
#include <math.h>
#include <stdint.h>

#define B_     8
#define N_     1024
#define DIM_   512
#define H_     8
#define DH_    64
#define INNER_ 512
#define MROWS  (B_*N_)          /* 8192 */
#define SCALE_ 0.125f
#define EPS_   1e-12f
#define SD_STRIDE 1028          /* f32 words per dots row (1024 + 4 pad); 4112B = 257*16 */

// Word permutation within 32-word (64 k-element) blocks:
//   natural o = ks*8 + s*4 + tig   ->   stored p = tig*8 + ks*2 + s
// so each lane's 8 fragment words per 64-k block are contiguous (2x LDG.128).
__device__ __forceinline__ int permw(int o)   { return (o&3)*8 + (o>>3)*2 + ((o>>2)&1); }
__device__ __forceinline__ int invperm(int w) { return ((w>>1)&3)*8 + (w&1)*4 + (w>>3); }

// ---------------- scratch -----------------------------------------------------
__device__ __align__(256) __nv_bfloat16 g_xhi[MROWS*DIM_],     g_xlo[MROWS*DIM_];
__device__ __align__(256) __nv_bfloat16 g_w1hi[3*INNER_*DIM_], g_w1lo[3*INNER_*DIM_]; // W_qkv^T perm
__device__ __align__(256) __nv_bfloat16 g_w2hi[DIM_*INNER_],   g_w2lo[DIM_*INNER_];   // W_out^T perm
__device__ __align__(256) __nv_bfloat16 g_qhi[B_*H_*N_*DH_],   g_qlo[B_*H_*N_*DH_];   // [b,h,n,dh] perm
__device__ __align__(256) __nv_bfloat16 g_khi[B_*H_*N_*DH_],   g_klo[B_*H_*N_*DH_];   // [b,h,n,dh] perm
__device__ __align__(256) __nv_bfloat16 g_vthi[B_*H_*DH_*N_],  g_vtlo[B_*H_*DH_*N_];  // [b,h,dh,n] perm
__device__ __align__(256) __nv_bfloat16 g_ahi[MROWS*INNER_],   g_alo[MROWS*INNER_];   // [m][inner] perm

// ---------------- helpers ------------------------------------------------------
__device__ __forceinline__ void mma_bf16(float* c, const uint32_t* a, uint32_t b0, uint32_t b1) {
    asm volatile("mma.sync.aligned.m16n8k16.row.col.f32.bf16.bf16.f32 "
        "{%0,%1,%2,%3}, {%4,%5,%6,%7}, {%8,%9}, {%0,%1,%2,%3};"
        : "+f"(c[0]), "+f"(c[1]), "+f"(c[2]), "+f"(c[3])
        : "r"(a[0]), "r"(a[1]), "r"(a[2]), "r"(a[3]), "r"(b0), "r"(b1));
}

// pack (x=even k, y=odd k): hi word (x low half) + exact residual lo word
__device__ __forceinline__ void split2(float x, float y, uint32_t& h, uint32_t& l) {
    uint32_t hh;
    asm("cvt.rn.bf16x2.f32 %0, %1, %2;" : "=r"(hh) : "f"(y), "f"(x));
    float hx = __uint_as_float(hh << 16);
    float hy = __uint_as_float(hh & 0xFFFF0000u);
    uint32_t ll;
    asm("cvt.rn.bf16x2.f32 %0, %1, %2;" : "=r"(ll) : "f"(y - hy), "f"(x - hx));
    h = hh; l = ll;
}
__device__ __forceinline__ void split1(float x, __nv_bfloat16& h, __nv_bfloat16& l) {
    h = __float2bfloat16_rn(x);
    l = __float2bfloat16_rn(x - __bfloat162float(h));
}
__device__ __forceinline__ uint32_t pack2(__nv_bfloat16 e0, __nv_bfloat16 e1) {
    return ((uint32_t)__bfloat16_as_ushort(e1) << 16) | __bfloat16_as_ushort(e0);
}

// ---------------- conversion kernels -------------------------------------------
// x [8192][512] -> permuted split rows
__global__ void k_split_x(const float* __restrict__ in) {
    int row = blockIdx.x*8 + (threadIdx.x >> 5);
    int lane = threadIdx.x & 31;
    const float* src = in + (size_t)row*DIM_;
    uint32_t* dh = (uint32_t*)g_xhi + (size_t)row*256;
    uint32_t* dl = (uint32_t*)g_xlo + (size_t)row*256;
    #pragma unroll
    for (int j = 0; j < 8; j++) {
        int p = lane + 32*j;
        int o = (p & ~31) | invperm(p & 31);
        float2 v = *(const float2*)(src + 2*o);
        __nv_bfloat16 h0,l0,h1,l1; split1(v.x,h0,l0); split1(v.y,h1,l1);
        dh[p] = pack2(h0,h1);
        dl[p] = pack2(l0,l1);
    }
}

// W [512 k][W n] -> transposed+permuted split [n][256 words]
__global__ void k_split_w(const float* __restrict__ in, int W,
                          __nv_bfloat16* __restrict__ outh, __nv_bfloat16* __restrict__ outl) {
    __shared__ float s[64][33];
    int n0 = blockIdx.x*32, k0 = blockIdx.y*64;
    int t = threadIdx.x;
    int nn = t & 31, kk = t >> 5;
    #pragma unroll
    for (int i = 0; i < 8; i++)
        s[kk + 8*i][nn] = in[(size_t)(k0 + kk + 8*i)*W + n0 + nn];
    __syncthreads();
    int nl = t >> 3, wg = (t & 7)*4;
    uint32_t* oh = (uint32_t*)outh + (size_t)(n0+nl)*256 + blockIdx.y*32;
    uint32_t* ol = (uint32_t*)outl + (size_t)(n0+nl)*256 + blockIdx.y*32;
    #pragma unroll
    for (int j = 0; j < 4; j++) {
        int w = wg + j;
        int o = invperm(w);
        __nv_bfloat16 h0,l0,h1,l1;
        split1(s[2*o][nl],   h0, l0);
        split1(s[2*o+1][nl], h1, l1);
        oh[w] = pack2(h0,h1);
        ol[w] = pack2(l0,l1);
    }
}

// ---------------- warp GEMM core: 64x32 C tile, K=512, permuted LDG.128 --------
// A/Bt rows = 256 words = 64 uint4 each (hi and lo arrays).
__device__ __forceinline__ void gemm_warp_64x32_p(
    const uint4* __restrict__ Ahi, const uint4* __restrict__ Alo,
    const uint4* __restrict__ Bhi, const uint4* __restrict__ Blo,
    int m_base, int n_base, int g, int tig, float c[4][4][4])
{
    for (int kb = 0; kb < 8; kb++) {
        uint32_t bh[4][8], bl[4][8];
        #pragma unroll
        for (int nt = 0; nt < 4; nt++) {
            const uint4* p = Bhi + (size_t)(n_base + nt*8 + g)*64 + kb*8 + tig*2;
            uint4 f0 = p[0], f1 = p[1];
            bh[nt][0]=f0.x; bh[nt][1]=f0.y; bh[nt][2]=f0.z; bh[nt][3]=f0.w;
            bh[nt][4]=f1.x; bh[nt][5]=f1.y; bh[nt][6]=f1.z; bh[nt][7]=f1.w;
            const uint4* q = Blo + (size_t)(n_base + nt*8 + g)*64 + kb*8 + tig*2;
            uint4 g0 = q[0], g1 = q[1];
            bl[nt][0]=g0.x; bl[nt][1]=g0.y; bl[nt][2]=g0.z; bl[nt][3]=g0.w;
            bl[nt][4]=g1.x; bl[nt][5]=g1.y; bl[nt][6]=g1.z; bl[nt][7]=g1.w;
        }
        #pragma unroll
        for (int mt = 0; mt < 4; mt++) {
            const uint4* pr = Ahi + (size_t)(m_base + mt*16 + g)*64 + kb*8 + tig*2;
            uint4 F0 = pr[0],     F1 = pr[1];
            uint4 S0 = pr[8*64],  S1 = pr[8*64 + 1];
            const uint4* ql = Alo + (size_t)(m_base + mt*16 + g)*64 + kb*8 + tig*2;
            uint4 G0 = ql[0],     G1 = ql[1];
            uint4 T0 = ql[8*64],  T1 = ql[8*64 + 1];
            uint32_t ah[4][4] = {
                {F0.x,S0.x,F0.y,S0.y},{F0.z,S0.z,F0.w,S0.w},
                {F1.x,S1.x,F1.y,S1.y},{F1.z,S1.z,F1.w,S1.w}};
            uint32_t al[4][4] = {
                {G0.x,T0.x,G0.y,T0.y},{G0.z,T0.z,G0.w,T0.w},
                {G1.x,T1.x,G1.y,T1.y},{G1.z,T1.z,G1.w,T1.w}};
            #pragma unroll
            for (int ks = 0; ks < 4; ks++)
                #pragma unroll
                for (int nt = 0; nt < 4; nt++) {
                    mma_bf16(c[mt][nt], ah[ks], bh[nt][ks*2], bh[nt][ks*2+1]);
                    mma_bf16(c[mt][nt], ah[ks], bl[nt][ks*2], bl[nt][ks*2+1]);
                    mma_bf16(c[mt][nt], al[ks], bh[nt][ks*2], bh[nt][ks*2+1]);
                }
        }
    }
}

// ---------------- kernel 1: qkv projection -------------------------------------
__global__ void __launch_bounds__(256) qkv_mma() {
    const int tid = threadIdx.x, w = tid >> 5, lane = tid & 31;
    const int g = lane >> 2, tig = lane & 3;
    const int m0 = blockIdx.y*128 + (w >> 2)*64;
    const int n0 = blockIdx.x*128 + (w & 3)*32;

    float c[4][4][4] = {};
    gemm_warp_64x32_p((const uint4*)g_xhi, (const uint4*)g_xlo,
                      (const uint4*)g_w1hi, (const uint4*)g_w1lo,
                      m0, n0, g, tig, c);

    #pragma unroll
    for (int mt = 0; mt < 4; mt++)
    #pragma unroll
    for (int nt = 0; nt < 4; nt++)
    #pragma unroll
    for (int half = 0; half < 2; half++) {
        int mg = m0 + mt*16 + g + half*8;
        int bb = mg >> 10, nn = mg & 1023;
        int ng = n0 + nt*8 + 2*tig;
        int sec = ng >> 9;
        int cc  = ng & 511;
        int hh  = cc >> 6, dd = cc & 63;
        float xv = c[mt][nt][half*2], yv = c[mt][nt][half*2+1];
        if (sec < 2) {
            uint32_t h, l; split2(xv, yv, h, l);
            int pw = permw(dd >> 1);
            size_t widx = (((size_t)bb*H_ + hh)*N_ + nn)*32 + pw;
            if (sec == 0) { ((uint32_t*)g_qhi)[widx] = h; ((uint32_t*)g_qlo)[widx] = l; }
            else          { ((uint32_t*)g_khi)[widx] = h; ((uint32_t*)g_klo)[widx] = l; }
        } else {
            __nv_bfloat16 h0,l0,h1,l1; split1(xv,h0,l0); split1(yv,h1,l1);
            int o = nn >> 1, hb = nn & 1;
            int pe = ((o & ~31) | permw(o & 31))*2 + hb;
            size_t base = (((size_t)bb*H_ + hh)*DH_ + dd)*N_;
            g_vthi[base + pe] = h0;       g_vtlo[base + pe] = l0;
            g_vthi[base + N_ + pe] = h1;  g_vtlo[base + N_ + pe] = l1;   // row dd+1
        }
    }
}

// ---------------- kernel 2: fused attention (512 threads) -----------------------
__global__ void __launch_bounds__(512) attn_mma(const float* __restrict__ spd,
                                                const float* __restrict__ head_mask) {
    extern __shared__ float sD[];      // 32 rows x SD_STRIDE f32
    const int tid = threadIdx.x, w = tid >> 5, lane = tid & 31;
    const int g = lane >> 2, tig = lane & 3;
    const int bb = blockIdx.z, hh = blockIdx.y, row0 = blockIdx.x*32;
    const int mw = w & 1, nw = w >> 1;          // mw 0..1, nw 0..7
    const int mrow = mw*16 + g;

    const uint4* Khi4 = (const uint4*)g_khi + (size_t)(bb*H_+hh)*N_*8;
    const uint4* Klo4 = (const uint4*)g_klo + (size_t)(bb*H_+hh)*N_*8;

    // ---- phase 1: dots = (Q K^T) * SCALE into sD (f32) ----
    uint32_t ah[4][4], al[4][4];
    {
        const uint4* qh = (const uint4*)g_qhi + ((size_t)(bb*H_+hh)*N_ + row0 + mrow)*8 + tig*2;
        const uint4* ql = (const uint4*)g_qlo + ((size_t)(bb*H_+hh)*N_ + row0 + mrow)*8 + tig*2;
        uint4 F0 = qh[0],    F1 = qh[1];
        uint4 S0 = qh[8*8],  S1 = qh[8*8+1];
        uint4 G0 = ql[0],    G1 = ql[1];
        uint4 T0 = ql[8*8],  T1 = ql[8*8+1];
        ah[0][0]=F0.x; ah[0][1]=S0.x; ah[0][2]=F0.y; ah[0][3]=S0.y;
        ah[1][0]=F0.z; ah[1][1]=S0.z; ah[1][2]=F0.w; ah[1][3]=S0.w;
        ah[2][0]=F1.x; ah[2][1]=S1.x; ah[2][2]=F1.y; ah[2][3]=S1.y;
        ah[3][0]=F1.z; ah[3][1]=S1.z; ah[3][2]=F1.w; ah[3][3]=S1.w;
        al[0][0]=G0.x; al[0][1]=T0.x; al[0][2]=G0.y; al[0][3]=T0.y;
        al[1][0]=G0.z; al[1][1]=T0.z; al[1][2]=G0.w; al[1][3]=T0.w;
        al[2][0]=G1.x; al[2][1]=T1.x; al[2][2]=G1.y; al[2][3]=T1.y;
        al[3][0]=G1.z; al[3][1]=T1.z; al[3][2]=G1.w; al[3][3]=T1.w;
    }
    #pragma unroll 2
    for (int nt = 0; nt < 16; nt++) {
        const int n0 = nw*128 + nt*8;
        const uint4* ph = Khi4 + (size_t)(n0+g)*8 + tig*2;
        const uint4* pl = Klo4 + (size_t)(n0+g)*8 + tig*2;
        uint4 F0 = ph[0], F1 = ph[1];
        uint4 G0 = pl[0], G1 = pl[1];
        uint32_t bhw[8] = {F0.x,F0.y,F0.z,F0.w,F1.x,F1.y,F1.z,F1.w};
        uint32_t blw[8] = {G0.x,G0.y,G0.z,G0.w,G1.x,G1.y,G1.z,G1.w};
        float c[4] = {0.f,0.f,0.f,0.f};
        #pragma unroll
        for (int ks = 0; ks < 4; ks++) {
            mma_bf16(c, ah[ks], bhw[ks*2], bhw[ks*2+1]);
            mma_bf16(c, ah[ks], blw[ks*2], blw[ks*2+1]);
            mma_bf16(c, al[ks], bhw[ks*2], bhw[ks*2+1]);
        }
        float2 v0 = { c[0]*SCALE_, c[1]*SCALE_ };
        float2 v1 = { c[2]*SCALE_, c[3]*SCALE_ };
        *(float2*)&sD[(size_t)mrow*SD_STRIDE + n0 + 2*tig]     = v0;
        *(float2*)&sD[(size_t)(mrow+8)*SD_STRIDE + n0 + 2*tig] = v1;
    }
    __syncthreads();

    // ---- phase 2: bias + exp + sum (no max-sub; |t| <~ 45, f32-safe), 2 rows/warp
    float msum = 0.f;
    #pragma unroll
    for (int i = 0; i < H_; i++) msum += head_mask[i];
    const float scale_m = head_mask[hh] * (float)H_ / msum;
    const int pl = permw(lane);

    #pragma unroll
    for (int rr = 0; rr < 2; rr++) {
        const int r = w*2 + rr, rg = row0 + r;
        float* drow = sD + (size_t)r*SD_STRIDE;
        const float* srow = spd + ((size_t)bb*N_ + rg)*N_;

        // pass 1: row norms
        float accd = 0.f, accp = 0.f;
        #pragma unroll 4
        for (int j = lane; j < N_; j += 32) {
            float d = drow[j], p = d*srow[j];
            accd += d*d; accp += p*p;
        }
        #pragma unroll
        for (int o = 16; o > 0; o >>= 1) {
            accd += __shfl_xor_sync(0xffffffffu, accd, o);
            accp += __shfl_xor_sync(0xffffffffu, accp, o);
        }
        const float rnorm = sqrtf(accd) / fmaxf(sqrtf(accp), EPS_);

        // pass 2: t = d*(1 + s*rnorm); e = exp(t); sum; store e
        float s = 0.f;
        #pragma unroll 4
        for (int j = lane; j < N_; j += 32) {
            float d = drow[j];
            float e = __expf(fmaf(d*srow[j], rnorm, d));
            drow[j] = e;
            s += e;
        }
        #pragma unroll
        for (int o = 16; o > 0; o >>= 1) s += __shfl_xor_sync(0xffffffffu, s, o);
        const float inv = scale_m / s;

        // pass 3: repack with scale: stage NATURAL word (32i + lane), write to
        // STORED position (32i + permw(lane)) as bf16 hi (words 0..511)/lo (+512)
        __syncwarp();
        float vb[32];
        #pragma unroll
        for (int i = 0; i < 16; i++) {
            float2 p = *(float2*)&drow[2*lane + 64*i];
            vb[2*i] = p.x*inv; vb[2*i+1] = p.y*inv;
        }
        __syncwarp();
        uint32_t* dw = (uint32_t*)drow;
        #pragma unroll
        for (int i = 0; i < 16; i++) {
            uint32_t h, l; split2(vb[2*i], vb[2*i+1], h, l);
            dw[i*32 + pl]       = h;
            dw[512 + i*32 + pl] = l;
        }
    }
    __syncthreads();

    // ---- phase 3: O = attn @ V  (A: permuted bf16 in smem, B: permuted V^T) ----
    const uint4* Vhi4 = (const uint4*)g_vthi + (size_t)(bb*H_+hh)*DH_*128;
    const uint4* Vlo4 = (const uint4*)g_vtlo + (size_t)(bb*H_+hh)*DH_*128;
    const int dh0 = nw*8;                       // 8 dh-cols per warp
    float oc[4] = {0.f,0.f,0.f,0.f};
    const uint4* r0 = (const uint4*)(sD + (size_t)mrow*SD_STRIDE);
    const uint4* r1 = (const uint4*)(sD + (size_t)(mrow+8)*SD_STRIDE);

    #pragma unroll 2
    for (int kb = 0; kb < 16; kb++) {
        const int ob = kb*8 + tig*2;
        uint4 F0 = r0[ob],       F1 = r0[ob+1];
        uint4 H0 = r1[ob],       H1 = r1[ob+1];
        uint4 G0 = r0[128+ob],   G1 = r0[128+ob+1];
        uint4 T0 = r1[128+ob],   T1 = r1[128+ob+1];
        uint32_t a4h[4][4] = {
            {F0.x,H0.x,F0.y,H0.y},{F0.z,H0.z,F0.w,H0.w},
            {F1.x,H1.x,F1.y,H1.y},{F1.z,H1.z,F1.w,H1.w}};
        uint32_t a4l[4][4] = {
            {G0.x,T0.x,G0.y,T0.y},{G0.z,T0.z,G0.w,T0.w},
            {G1.x,T1.x,G1.y,T1.y},{G1.z,T1.z,G1.w,T1.w}};
        const uint4* ph = Vhi4 + (size_t)(dh0 + g)*128 + ob;
        const uint4* pv = Vlo4 + (size_t)(dh0 + g)*128 + ob;
        uint4 P0 = ph[0], P1 = ph[1];
        uint4 Q0 = pv[0], Q1 = pv[1];
        uint32_t bhw[8] = {P0.x,P0.y,P0.z,P0.w,P1.x,P1.y,P1.z,P1.w};
        uint32_t blw[8] = {Q0.x,Q0.y,Q0.z,Q0.w,Q1.x,Q1.y,Q1.z,Q1.w};
        #pragma unroll
        for (int ks = 0; ks < 4; ks++) {
            mma_bf16(oc, a4h[ks], bhw[ks*2], bhw[ks*2+1]);
            mma_bf16(oc, a4h[ks], blw[ks*2], blw[ks*2+1]);
            mma_bf16(oc, a4l[ks], bhw[ks*2], bhw[ks*2+1]);
        }
    }

    #pragma unroll
    for (int half = 0; half < 2; half++) {
        int rg  = row0 + mw*16 + g + half*8;
        size_t mg = (size_t)bb*N_ + rg;
        int rcol = dh0 + 2*tig;                 // 0..62 within head
        uint32_t h, l; split2(oc[half*2], oc[half*2+1], h, l);
        int pw = hh*32 + permw(rcol >> 1);
        size_t widx = mg*256 + pw;
        ((uint32_t*)g_ahi)[widx] = h; ((uint32_t*)g_alo)[widx] = l;
    }
}

// ---------------- kernel 3: output projection ----------------------------------
__global__ void __launch_bounds__(256) out_mma(const float* __restrict__ bout,
                                               float* __restrict__ out) {
    const int tid = threadIdx.x, w = tid >> 5, lane = tid & 31;
    const int g = lane >> 2, tig = lane & 3;
    const int m0 = blockIdx.y*128 + (w >> 2)*64;
    const int n0 = blockIdx.x*128 + (w & 3)*32;

    float c[4][4][4] = {};
    gemm_warp_64x32_p((const uint4*)g_ahi, (const uint4*)g_alo,
                      (const uint4*)g_w2hi, (const uint4*)g_w2lo,
                      m0, n0, g, tig, c);

    #pragma unroll
    for (int mt = 0; mt < 4; mt++)
    #pragma unroll
    for (int nt = 0; nt < 4; nt++)
    #pragma unroll
    for (int half = 0; half < 2; half++) {
        int mg = m0 + mt*16 + g + half*8;
        int ng = n0 + nt*8 + 2*tig;
        float2 v = { c[mt][nt][half*2]   + bout[ng],
                     c[mt][nt][half*2+1] + bout[ng+1] };
        *(float2*)(out + (size_t)mg*DIM_ + ng) = v;
    }
}

// ---------------- launch ---------------------------------------------------------
extern "C" void kernel_launch(void* const* d_in, const int* in_sizes, int n_in,
                              void* d_out, int out_size) {
    const float* x         = (const float*)d_in[0];
    const float* spd       = (const float*)d_in[1];
    const float* head_mask = (const float*)d_in[2];
    const float* W_qkv     = (const float*)d_in[3];
    const float* W_out     = (const float*)d_in[4];
    const float* b_out     = (const float*)d_in[5];
    float* out = (float*)d_out;

    __nv_bfloat16 *w1h, *w1l, *w2h, *w2l;
    cudaGetSymbolAddress((void**)&w1h, g_w1hi); cudaGetSymbolAddress((void**)&w1l, g_w1lo);
    cudaGetSymbolAddress((void**)&w2h, g_w2hi); cudaGetSymbolAddress((void**)&w2l, g_w2lo);

    k_split_x<<<MROWS/8, 256>>>(x);
    k_split_w<<<dim3(48, 8), 256>>>(W_qkv, 3*INNER_, w1h, w1l);
    k_split_w<<<dim3(16, 8), 256>>>(W_out, DIM_,     w2h, w2l);

    qkv_mma<<<dim3(12, 64), 256>>>();

    size_t smem = (size_t)32*SD_STRIDE*sizeof(float);   // 131584 B
    cudaFuncSetAttribute(attn_mma, cudaFuncAttributeMaxDynamicSharedMemorySize, (int)smem);
    attn_mma<<<dim3(N_/32, H_, B_), 512, smem>>>(spd, head_mask);

    out_mma<<<dim3(4, 64), 256>>>(b_out, out);
}